// round 14
// baseline (speedup 1.0000x reference)
#include <cuda_runtime.h>
#include <cuda_fp16.h>
#include <math.h>
#include <stdint.h>

#define BATCH 16
#define CH 512
#define HW 4096
#define KTOT 4608           // 512 c * 9 taps
#define KITERS 72           // 4608 / 64
#define GTHR 256
#define STAGES 3
#define A_BYTES 16384       // 128 x 64 fp16
#define B_BYTES 16384       // 128 x 64 fp16
#define STAGE_BYTES (A_BYTES + B_BYTES)
#define SMEM_GEMM (STAGES * STAGE_BYTES)   // 96KB per CTA, 2 CTAs/SM

// ---------------- scratch ----------------
__device__ float g_s[BATCH * CH];
__device__ float g_s2[BATCH * CH];
__device__ float g_dcoef[BATCH * CH];
__device__ float g_wsq[CH * CH];
__device__ float g_rwp[BATCH * 3 * CH];     // rgb_w[ch,o] * s2[b,o]
__device__ __half g_cwh[CH * KTOT];         // conv_w fp16 [o][ck]  (18.8MB, L2-resident)
__device__ __half g_sexp[BATCH * KTOT];     // styles expanded to k space [b][ck]
__device__ __half g_B[HW * KTOT];           // im2col patches  [p][ck]

__device__ __forceinline__ uint32_t s2u(const void* p) {
    return (uint32_t)__cvta_generic_to_shared(p);
}
__device__ __forceinline__ uint32_t swzoff(uint32_t row, uint32_t chunk) {
    return row * 128u + ((chunk ^ (row & 7u)) << 4);
}
__device__ __forceinline__ void cpa16(uint32_t s, const void* g) {
    asm volatile("cp.async.cg.shared.global [%0], [%1], 16;" :: "r"(s), "l"(g));
}
__device__ __forceinline__ void sts128(uint32_t s, uint4 v) {
    asm volatile("st.shared.v4.b32 [%0], {%1,%2,%3,%4};"
                 :: "r"(s), "r"(v.x), "r"(v.y), "r"(v.z), "r"(v.w));
}
__device__ __forceinline__ void ldm4(uint32_t addr, uint32_t& r0, uint32_t& r1,
                                     uint32_t& r2, uint32_t& r3) {
    asm volatile("ldmatrix.sync.aligned.m8n8.x4.shared.b16 {%0,%1,%2,%3}, [%4];"
                 : "=r"(r0), "=r"(r1), "=r"(r2), "=r"(r3) : "r"(addr));
}
__device__ __forceinline__ void hmma(float* d, const uint32_t* a, const uint32_t* bf) {
    asm volatile(
        "mma.sync.aligned.m16n8k16.row.col.f32.f16.f16.f32 "
        "{%0,%1,%2,%3}, {%4,%5,%6,%7}, {%8,%9}, {%0,%1,%2,%3};"
        : "+f"(d[0]), "+f"(d[1]), "+f"(d[2]), "+f"(d[3])
        : "r"(a[0]), "r"(a[1]), "r"(a[2]), "r"(a[3]), "r"(bf[0]), "r"(bf[1]));
}

// ---------------- prep0: styles + wsq + img bias init ----------------
__global__ void k_prep0(const float* __restrict__ ws, const float* __restrict__ caw,
                        const float* __restrict__ cab, const float* __restrict__ raw,
                        const float* __restrict__ rab, const float* __restrict__ cw,
                        const float* __restrict__ rgbb, float* __restrict__ img) {
    if (blockIdx.x < 1024) {
        int widx = blockIdx.x * 8 + (threadIdx.x >> 5);
        int lane = threadIdx.x & 31;
        int b = widx >> 9, c = widx & 511;
        const float* w0 = ws + b * 1024;
        const float* w1 = w0 + 512;
        const float* ca = caw + c * 512;
        const float* ra = raw + c * 512;
        float a1 = 0.f, a2 = 0.f;
        for (int d = lane; d < 512; d += 32) {
            a1 = fmaf(w0[d], ca[d], a1);
            a2 = fmaf(w1[d], ra[d], a2);
        }
        #pragma unroll
        for (int o = 16; o; o >>= 1) {
            a1 += __shfl_xor_sync(0xffffffffu, a1, o);
            a2 += __shfl_xor_sync(0xffffffffu, a2, o);
        }
        if (lane == 0) {
            g_s[b * 512 + c] = a1 + cab[c];
            g_s2[b * 512 + c] = (a2 + rab[c]) * 0.04419417382415922f;
        }
    } else if (blockIdx.x < 2048) {
        int idx = (blockIdx.x - 1024) * 256 + threadIdx.x;
        const float* p = cw + (size_t)idx * 9;
        float s = 0.f;
        #pragma unroll
        for (int k = 0; k < 9; k++) s = fmaf(p[k], p[k], s);
        g_wsq[idx] = s;
    } else {
        // img bias init: 16*3*4096 = 196608 elems over 768 blocks
        int idx = (blockIdx.x - 2048) * 256 + threadIdx.x;
        int ch = (idx >> 12) % 3;
        img[idx] = rgbb[ch];
    }
}

// ---------------- dcoef + rwp + s_exp ----------------
__global__ void k_dcoef(const float* __restrict__ rgbw) {
    if (blockIdx.x < 1024) {
        int widx = blockIdx.x * 8 + (threadIdx.x >> 5);
        int lane = threadIdx.x & 31;
        int b = widx >> 9, o = widx & 511;
        const float* wq = g_wsq + o * 512;
        const float* sp = g_s + b * 512;
        float a = 0.f;
        for (int c = lane; c < 512; c += 32) {
            float sv = sp[c];
            a = fmaf(wq[c] * sv, sv, a);
        }
        #pragma unroll
        for (int off = 16; off; off >>= 1) a += __shfl_xor_sync(0xffffffffu, a, off);
        if (!lane) g_dcoef[b * 512 + o] = rsqrtf(a + 1e-8f);
    } else if (blockIdx.x < 1120) {
        // rwp[b][ch][o] = rgbw[ch*512+o] * g_s2[b*512+o]; 24576 elems over 96 blocks
        int idx = (blockIdx.x - 1024) * 256 + threadIdx.x;
        int b = idx / 1536;
        int r = idx - b * 1536;
        int ch = r >> 9, o = r & 511;
        g_rwp[idx] = rgbw[ch * 512 + o] * g_s2[b * 512 + o];
    } else {
        // s_exp[b][ck] = half(g_s[b][ck/9]); 73728 halves, x4 per thread, 72 blocks
        int idx = (blockIdx.x - 1120) * 256 + threadIdx.x;   // [0, 18432)
        int ck4 = (idx % 1152) * 4;
        int b = idx / 1152;
        __half h[4];
        #pragma unroll
        for (int j = 0; j < 4; j++) {
            int c = (unsigned)(ck4 + j) / 9u;
            h[j] = __float2half_rn(g_s[b * 512 + c]);
        }
        *(uint2*)(g_sexp + (size_t)b * KTOT + ck4) = *(const uint2*)h;
    }
}

// ---------------- prep1: cwh (fp16 conv_w) + B im2col prep ----------------
__global__ void k_prep1(const float* __restrict__ cw, const float* __restrict__ cst) {
    if (blockIdx.x < 1152) {
        // cwh: 512*4608 halves, 8 per thread
        int idx = blockIdx.x * 256 + threadIdx.x;            // [0, 294912)
        const float* wp = cw + (size_t)idx * 8;
        float4 f0 = *(const float4*)(wp);
        float4 f1 = *(const float4*)(wp + 4);
        __half h[8];
        h[0] = __float2half_rn(f0.x); h[1] = __float2half_rn(f0.y);
        h[2] = __float2half_rn(f0.z); h[3] = __float2half_rn(f0.w);
        h[4] = __float2half_rn(f1.x); h[5] = __float2half_rn(f1.y);
        h[6] = __float2half_rn(f1.z); h[7] = __float2half_rn(f1.w);
        *(uint4*)(g_cwh + (size_t)idx * 8) = *(const uint4*)h;
    } else {
        int idx = (blockIdx.x - 1152) * 256 + threadIdx.x;   // over HW*KTOT/8
        int ck8 = (idx % (KTOT / 8)) * 8;
        int p = idx / (KTOT / 8);
        int py = p >> 6, px = p & 63;
        __half h[8];
        #pragma unroll
        for (int j = 0; j < 8; j++) {
            int ck = ck8 + j;
            int c = (unsigned)ck / 9u;
            int k = ck - c * 9;
            int ky = (unsigned)k / 3u;
            int kx = k - ky * 3;
            int yy = py + ky - 1;
            int xx = px + kx - 1;
            float v = 0.f;
            if ((unsigned)yy < 64u && (unsigned)xx < 64u)
                v = cst[c * 4096 + yy * 64 + xx];
            h[j] = __float2half_rn(v);
        }
        *(uint4*)(g_B + (size_t)idx * 8) = *(const uint4*)h;
    }
}

// ---------------- main GEMM: CTA 128x128, warp 64x32, 2 CTAs/SM, fused RGB ----------------
// A tile built in-kernel: cwh * s_exp  (no 75MB g_A intermediate)
__global__ __launch_bounds__(GTHR, 2)
void k_gemm(const float* __restrict__ nzc, const float* __restrict__ nzs,
            const float* __restrict__ cb, float* __restrict__ out,
            float* __restrict__ img) {
    extern __shared__ char smem[];
    const uint32_t sb = s2u(smem);

    const int tid = threadIdx.x;
    const int wid = tid >> 5;
    const int lane = tid & 31;
    const int wm = wid & 1;        // 2 m-bands of 64
    const int wn = wid >> 1;       // 4 n-bands of 32

    const int b = blockIdx.z;
    const int obase = blockIdx.y * 128;
    const int pbase = blockIdx.x * 128;

    // per-thread fill coordinates (fixed across iters)
    const int frow = tid >> 1;                 // 0..127 (2 chunk-slots per row pair)
    const uint32_t fcv0 = (tid & 1) * 4;       // chunks 0..3 or 4..7 handled below
    const char* Bg = (const char*)(g_B + (size_t)pbase * KTOT);
    const __half* Aw = g_cwh + (size_t)(obase) * KTOT;
    const __half* Sx = g_sexp + (size_t)b * KTOT;

    float acc[4][4][4];
    #pragma unroll
    for (int mi = 0; mi < 4; mi++)
        #pragma unroll
        for (int nj = 0; nj < 4; nj++)
            #pragma unroll
            for (int q = 0; q < 4; q++) acc[mi][nj][q] = 0.f;

    // A fill: synchronous LDG(cwh) * LDG(s_exp) -> STS.128 (visible after next sync)
    #define FILL_A(KI, STG) do {                                                   \
        uint32_t sA = sb + (STG) * STAGE_BYTES;                                    \
        _Pragma("unroll")                                                          \
        for (int j = 0; j < 4; j++) {                                              \
            int idx = tid + j * GTHR;                                              \
            uint32_t row = idx >> 3, cv = idx & 7;                                 \
            const __half* ap = Aw + (size_t)row * KTOT + (KI) * 64 + cv * 8;       \
            const __half* sp = Sx + (KI) * 64 + cv * 8;                            \
            uint4 av = *(const uint4*)ap;                                          \
            uint4 sv = *(const uint4*)sp;                                          \
            half2* a2 = (half2*)&av;                                               \
            const half2* s2p = (const half2*)&sv;                                  \
            a2[0] = __hmul2(a2[0], s2p[0]);                                        \
            a2[1] = __hmul2(a2[1], s2p[1]);                                        \
            a2[2] = __hmul2(a2[2], s2p[2]);                                        \
            a2[3] = __hmul2(a2[3], s2p[3]);                                        \
            sts128(sA + swzoff(row, cv), av);                                      \
        }                                                                          \
    } while (0)

    // B fill: cp.async (one commit group per call)
    #define FILL_B(KI, STG) do {                                                   \
        size_t kb = (size_t)(KI) * 128;                                            \
        uint32_t sBs = sb + (STG) * STAGE_BYTES + A_BYTES;                         \
        _Pragma("unroll")                                                          \
        for (int j = 0; j < 4; j++) {                                              \
            int idx = tid + j * GTHR;                                              \
            uint32_t row = idx >> 3, cv = idx & 7;                                 \
            cpa16(sBs + swzoff(row, cv),                                           \
                  Bg + (size_t)row * (KTOT * 2) + kb + cv * 16);                   \
        }                                                                          \
        asm volatile("cp.async.commit_group;" ::: "memory");                       \
    } while (0)

    FILL_A(0, 0); FILL_B(0, 0);
    FILL_A(1, 1); FILL_B(1, 1);

    int stg = 0;
    for (int i = 0; i < KITERS; i++) {
        asm volatile("cp.async.wait_group 1;" ::: "memory");
        __syncthreads();

        if (i + 2 < KITERS) {
            int ns = stg + 2;
            if (ns >= STAGES) ns -= STAGES;
            FILL_A(i + 2, ns);
            FILL_B(i + 2, ns);
        } else {
            asm volatile("cp.async.commit_group;" ::: "memory");
        }

        const uint32_t sA = sb + stg * STAGE_BYTES;
        const uint32_t sBs = sA + A_BYTES;

        #pragma unroll
        for (int k16 = 0; k16 < 4; k16++) {
            const uint32_t kc = k16 * 2;
            uint32_t a[4][4], br[2][4];
            #pragma unroll
            for (int mi = 0; mi < 4; mi++) {
                uint32_t row = wm * 64 + mi * 16 + (lane & 15);
                uint32_t chunk = kc + (lane >> 4);
                ldm4(sA + swzoff(row, chunk), a[mi][0], a[mi][1], a[mi][2], a[mi][3]);
            }
            #pragma unroll
            for (int njp = 0; njp < 2; njp++) {
                uint32_t row = wn * 32 + njp * 16 + ((lane >> 4) << 3) + (lane & 7);
                uint32_t chunk = kc + ((lane >> 3) & 1);
                ldm4(sBs + swzoff(row, chunk), br[njp][0], br[njp][1], br[njp][2], br[njp][3]);
            }
            #pragma unroll
            for (int mi = 0; mi < 4; mi++)
                #pragma unroll
                for (int nj = 0; nj < 4; nj++)
                    hmma(acc[mi][nj], a[mi], &br[nj >> 1][(nj & 1) * 2]);
        }
        stg = (stg + 1 == STAGES) ? 0 : stg + 1;
    }

    // ---------------- fused epilogue: x (demod/noise/bias/lrelu) + rgb partials ----------------
    const float nst = nzs[0];
    const float gain = 1.4142135623730951f;
    const int r0 = lane >> 2;
    const int cpair = (lane & 3) * 2;

    float nzv[4][2];
    #pragma unroll
    for (int nj = 0; nj < 4; nj++) {
        int p = pbase + wn * 32 + nj * 8 + cpair;
        nzv[nj][0] = nzc[p] * nst;
        nzv[nj][1] = nzc[p + 1] * nst;
    }

    float pr[3][8];   // [ch][nj*2+parity] rgb partials over this thread's 8 o's
    #pragma unroll
    for (int ch = 0; ch < 3; ch++)
        #pragma unroll
        for (int j = 0; j < 8; j++) pr[ch][j] = 0.f;

    const float* rwp = g_rwp + b * 1536;

    #pragma unroll
    for (int mi = 0; mi < 4; mi++) {
        #pragma unroll
        for (int h = 0; h < 2; h++) {
            int o = obase + wm * 64 + mi * 16 + h * 8 + r0;
            float dc = g_dcoef[b * 512 + o];
            float bias = cb[o];
            float rw0 = rwp[o], rw1 = rwp[512 + o], rw2 = rwp[1024 + o];
            float* orow = out + (size_t)(b * 512 + o) * HW;
            #pragma unroll
            for (int nj = 0; nj < 4; nj++) {
                int p = pbase + wn * 32 + nj * 8 + cpair;
                float z0 = fmaf(acc[mi][nj][2 * h],     dc, nzv[nj][0] + bias);
                float z1 = fmaf(acc[mi][nj][2 * h + 1], dc, nzv[nj][1] + bias);
                float2 v;
                v.x = (z0 > 0.f ? z0 : 0.2f * z0) * gain;
                v.y = (z1 > 0.f ? z1 : 0.2f * z1) * gain;
                *(float2*)(orow + p) = v;
                pr[0][nj * 2]     = fmaf(rw0, v.x, pr[0][nj * 2]);
                pr[0][nj * 2 + 1] = fmaf(rw0, v.y, pr[0][nj * 2 + 1]);
                pr[1][nj * 2]     = fmaf(rw1, v.x, pr[1][nj * 2]);
                pr[1][nj * 2 + 1] = fmaf(rw1, v.y, pr[1][nj * 2 + 1]);
                pr[2][nj * 2]     = fmaf(rw2, v.x, pr[2][nj * 2]);
                pr[2][nj * 2 + 1] = fmaf(rw2, v.y, pr[2][nj * 2 + 1]);
            }
        }
    }

    // rgb reduction: shuffle over the 8 lanes sharing a pixel, then lanes 0-3 red.add
    float* imgb = img + (size_t)b * 3 * HW + pbase;
    #pragma unroll
    for (int ch = 0; ch < 3; ch++) {
        #pragma unroll
        for (int j = 0; j < 8; j++) {
            float v = pr[ch][j];
            v += __shfl_down_sync(0xffffffffu, v, 16);
            v += __shfl_down_sync(0xffffffffu, v, 8);
            v += __shfl_down_sync(0xffffffffu, v, 4);
            if (lane < 4) {
                int px = wn * 32 + (j >> 1) * 8 + lane * 2 + (j & 1);
                atomicAdd(imgb + (size_t)ch * HW + px, v);
            }
        }
    }
}

extern "C" void kernel_launch(void* const* d_in, const int* in_sizes, int n_in,
                              void* d_out, int out_size) {
    const float* ws   = (const float*)d_in[0];
    const float* cst  = (const float*)d_in[1];
    const float* cw   = (const float*)d_in[2];
    const float* cb   = (const float*)d_in[3];
    const float* caw  = (const float*)d_in[4];
    const float* cab  = (const float*)d_in[5];
    const float* nzc  = (const float*)d_in[6];
    const float* nzs  = (const float*)d_in[7];
    const float* rgbw = (const float*)d_in[8];
    const float* rgbb = (const float*)d_in[9];
    const float* raw  = (const float*)d_in[10];
    const float* rab  = (const float*)d_in[11];
    float* out = (float*)d_out;
    float* img = out + (size_t)BATCH * CH * HW;

    cudaFuncSetAttribute(k_gemm, cudaFuncAttributeMaxDynamicSharedMemorySize, SMEM_GEMM);

    k_prep0<<<2048 + 768, 256>>>(ws, caw, cab, raw, rab, cw, rgbb, img);  // launch 0
    k_dcoef<<<1024 + 96 + 72, 256>>>(rgbw);                               // launch 1
    k_prep1<<<1152 + 9216, 256>>>(cw, cst);                               // launch 2
    dim3 g(HW / 128, CH / 128, BATCH);                                    // (32, 4, 16)
    k_gemm<<<g, GTHR, SMEM_GEMM>>>(nzc, nzs, cb, out, img);               // launch 3 (profiled)
}

// round 16
// speedup vs baseline: 1.3204x; 1.3204x over previous
#include <cuda_runtime.h>
#include <cuda_fp16.h>
#include <math.h>
#include <stdint.h>

#define BATCH 16
#define CH 512
#define HW 4096
#define OT 64            // o per CTA
#define PT 16            // pixels per CTA
#define CC 16            // channels per chunk
#define NCHUNK 32
#define FTHR 256
#define ZPITCH 2064      // 1024 m * 2B + 16B pad (kills mod-128 collapse)

// smem map (dynamic):
#define SM_W 0                         // W operand, 2 x 32768
#define SM_B 65536                     // patch operand, 2 x 8192
#define SM_Z 81920                     // Z, 2 x 33024 (16 ch * ZPITCH)
#define SM_S 147968                    // s fp16, 16 rows x 1040B
#define SM_TOTAL (147968 + 16640)      // 164608

// ---------------- scratch ----------------
__device__ float g_s[BATCH * CH];
__device__ float g_s2[BATCH * CH];
__device__ float g_dcoef[BATCH * CH];
__device__ float g_wsq[CH * CH];
__device__ float g_rwp[BATCH * 3 * CH];       // rgb_w[ch,o] * s2[b,o]
__device__ __half g_Wp[128 * 512 * 64];       // [cgroup][o][4ch x 16k] (8.4MB)
__device__ __half g_Bp[128 * 4096 * 64];      // [cgroup][p][4ch x 16k] (67MB)

__device__ __forceinline__ uint32_t s2u(const void* p) {
    return (uint32_t)__cvta_generic_to_shared(p);
}
__device__ __forceinline__ void cpa16(uint32_t s, const void* g) {
    asm volatile("cp.async.cg.shared.global [%0], [%1], 16;" :: "r"(s), "l"(g));
}
__device__ __forceinline__ void ldm4(uint32_t addr, uint32_t* r) {
    asm volatile("ldmatrix.sync.aligned.m8n8.x4.shared.b16 {%0,%1,%2,%3}, [%4];"
                 : "=r"(r[0]), "=r"(r[1]), "=r"(r[2]), "=r"(r[3]) : "r"(addr));
}
__device__ __forceinline__ void ldm4t(uint32_t addr, uint32_t* r) {
    asm volatile("ldmatrix.sync.aligned.m8n8.x4.trans.shared.b16 {%0,%1,%2,%3}, [%4];"
                 : "=r"(r[0]), "=r"(r[1]), "=r"(r[2]), "=r"(r[3]) : "r"(addr));
}
__device__ __forceinline__ void hmma(float* d, const uint32_t* a, const uint32_t* bf) {
    asm volatile(
        "mma.sync.aligned.m16n8k16.row.col.f32.f16.f16.f32 "
        "{%0,%1,%2,%3}, {%4,%5,%6,%7}, {%8,%9}, {%0,%1,%2,%3};"
        : "+f"(d[0]), "+f"(d[1]), "+f"(d[2]), "+f"(d[3])
        : "r"(a[0]), "r"(a[1]), "r"(a[2]), "r"(a[3]), "r"(bf[0]), "r"(bf[1]));
}

// ---------------- prep0: styles + wsq + img bias init ----------------
__global__ void k_prep0(const float* __restrict__ ws, const float* __restrict__ caw,
                        const float* __restrict__ cab, const float* __restrict__ raw,
                        const float* __restrict__ rab, const float* __restrict__ cw,
                        const float* __restrict__ rgbb, float* __restrict__ img) {
    if (blockIdx.x < 1024) {
        int widx = blockIdx.x * 8 + (threadIdx.x >> 5);
        int lane = threadIdx.x & 31;
        int b = widx >> 9, c = widx & 511;
        const float* w0 = ws + b * 1024;
        const float* w1 = w0 + 512;
        const float* ca = caw + c * 512;
        const float* ra = raw + c * 512;
        float a1 = 0.f, a2 = 0.f;
        for (int d = lane; d < 512; d += 32) {
            a1 = fmaf(w0[d], ca[d], a1);
            a2 = fmaf(w1[d], ra[d], a2);
        }
        #pragma unroll
        for (int o = 16; o; o >>= 1) {
            a1 += __shfl_xor_sync(0xffffffffu, a1, o);
            a2 += __shfl_xor_sync(0xffffffffu, a2, o);
        }
        if (lane == 0) {
            g_s[b * 512 + c] = a1 + cab[c];
            g_s2[b * 512 + c] = (a2 + rab[c]) * 0.04419417382415922f;
        }
    } else if (blockIdx.x < 2048) {
        int idx = (blockIdx.x - 1024) * 256 + threadIdx.x;
        const float* p = cw + (size_t)idx * 9;
        float s = 0.f;
        #pragma unroll
        for (int k = 0; k < 9; k++) s = fmaf(p[k], p[k], s);
        g_wsq[idx] = s;
    } else {
        int idx = (blockIdx.x - 2048) * 256 + threadIdx.x;
        int ch = (idx >> 12) % 3;
        img[idx] = rgbb[ch];
    }
}

// ---------------- dcoef + rwp ----------------
__global__ void k_dcoef(const float* __restrict__ rgbw) {
    if (blockIdx.x < 1024) {
        int widx = blockIdx.x * 8 + (threadIdx.x >> 5);
        int lane = threadIdx.x & 31;
        int b = widx >> 9, o = widx & 511;
        const float* wq = g_wsq + o * 512;
        const float* sp = g_s + b * 512;
        float a = 0.f;
        for (int c = lane; c < 512; c += 32) {
            float sv = sp[c];
            a = fmaf(wq[c] * sv, sv, a);
        }
        #pragma unroll
        for (int off = 16; off; off >>= 1) a += __shfl_xor_sync(0xffffffffu, a, off);
        if (!lane) g_dcoef[b * 512 + o] = rsqrtf(a + 1e-8f);
    } else {
        int idx = (blockIdx.x - 1024) * 256 + threadIdx.x;
        int b = idx / 1536;
        int r = idx - b * 1536;
        int ch = r >> 9, o = r & 511;
        g_rwp[idx] = rgbw[ch * 512 + o] * g_s2[b * 512 + o];
    }
}

// ---------------- prep1: pack W and patches into k16-padded 4ch rows ----------------
__global__ void k_prep1(const float* __restrict__ cw, const float* __restrict__ cst) {
    if (blockIdx.x < 2048) {
        // Wp: [cg][o][pos 64]; idx over 4.19M/8
        int idx = blockIdx.x * 256 + threadIdx.x;
        int pos8 = (idx & 7) * 8;
        int rem = idx >> 3;          // cg*512 + o
        int o = rem & 511;
        int cg = rem >> 9;
        __half h[8];
        #pragma unroll
        for (int j = 0; j < 8; j++) {
            int pos = pos8 + j;
            int ch = cg * 4 + (pos >> 4);
            int k = pos & 15;
            float v = (k < 9) ? cw[(size_t)o * 4608 + ch * 9 + k] : 0.f;
            h[j] = __float2half_rn(v);
        }
        *(uint4*)(g_Wp + (size_t)idx * 8) = *(const uint4*)h;
    } else {
        // Bp: [cg][p][pos 64]; idx over 33.5M/8
        int idx = (blockIdx.x - 2048) * 256 + threadIdx.x;
        int pos8 = (idx & 7) * 8;
        int rem = idx >> 3;          // cg*4096 + p
        int p = rem & 4095;
        int cg = rem >> 12;
        int py = p >> 6, px = p & 63;
        __half h[8];
        #pragma unroll
        for (int j = 0; j < 8; j++) {
            int pos = pos8 + j;
            int ch = cg * 4 + (pos >> 4);
            int k = pos & 15;
            float v = 0.f;
            if (k < 9) {
                int ky = (unsigned)k / 3u;
                int kx = k - ky * 3;
                int yy = py + ky - 1;
                int xx = px + kx - 1;
                if ((unsigned)yy < 64u && (unsigned)xx < 64u)
                    v = cst[ch * 4096 + yy * 64 + xx];
            }
            h[j] = __float2half_rn(v);
        }
        *(uint4*)(g_Bp + (size_t)idx * 8) = *(const uint4*)h;
    }
}

// ---------------- factorized two-stage kernel ----------------
__global__ __launch_bounds__(FTHR, 1)
void k_fact(const float* __restrict__ nzc, const float* __restrict__ nzs,
            const float* __restrict__ cb, float* __restrict__ out,
            float* __restrict__ img) {
    extern __shared__ char smem[];
    const uint32_t sb = s2u(smem);
    const int tid = threadIdx.x;
    const int wid = tid >> 5;
    const int lane = tid & 31;
    const int pbase = blockIdx.x * PT;
    const int obase = blockIdx.y * OT;

    // s fp16 into padded smem rows (used after >=1 sync)
    for (int i = tid; i < 16 * 256; i += FTHR) {
        int b = i >> 8, c2 = (i & 255) * 2;
        __half2 v = __floats2half2_rn(g_s[b * 512 + c2], g_s[b * 512 + c2 + 1]);
        *(__half2*)(smem + SM_S + b * 1040 + c2 * 2) = v;
    }

    float acc[8][2][4];
    #pragma unroll
    for (int mi = 0; mi < 8; mi++)
        #pragma unroll
        for (int nb = 0; nb < 2; nb++)
            #pragma unroll
            for (int q = 0; q < 4; q++) acc[mi][nb][q] = 0.f;

    // fill W(32KB) + patches(8KB) for chunk CHK into buffer S
    #define FILLWB(CHK, S) do {                                                   \
        int cg0 = (CHK) * 4;                                                      \
        _Pragma("unroll")                                                         \
        for (int j = 0; j < 8; j++) {                                             \
            int idx = tid + j * FTHR;                                             \
            uint32_t row = idx >> 3, c16 = idx & 7;                               \
            int oo = row & 63, cgi = row >> 6;                                    \
            const char* src = (const char*)g_Wp +                                 \
                (((size_t)(cg0 + cgi) * 512 + obase + oo) << 7) + c16 * 16;       \
            cpa16(sb + SM_W + (S) * 32768 + row * 128 +                           \
                  ((c16 ^ (row & 7)) << 4), src);                                 \
        }                                                                         \
        _Pragma("unroll")                                                         \
        for (int j = 0; j < 2; j++) {                                             \
            int idx = tid + j * FTHR;                                             \
            uint32_t row = idx >> 3, c16 = idx & 7;                               \
            int pp = row & 15, cgi = row >> 4;                                    \
            const char* src = (const char*)g_Bp +                                 \
                (((size_t)(cg0 + cgi) * 4096 + pbase + pp) << 7) + c16 * 16;      \
            cpa16(sb + SM_B + (S) * 8192 + row * 128 +                            \
                  ((c16 ^ (row & 7)) << 4), src);                                 \
        }                                                                         \
        asm volatile("cp.async.commit_group;" ::: "memory");                      \
    } while (0)

    FILLWB(0, 0);

    for (int chk = 0; chk < NCHUNK; chk++) {
        asm volatile("cp.async.wait_group 0;" ::: "memory");
        __syncthreads();
        if (chk + 1 < NCHUNK) FILLWB(chk + 1, (chk + 1) & 1);

        const int s = chk & 1;
        const uint32_t wbase = sb + SM_W + s * 32768;
        const uint32_t bbase = sb + SM_B + s * 8192;
        const uint32_t zbase = sb + SM_Z + s * 33024;

        // ---- stage 1: each warp computes 2 channels of Z[o64,p16] ----
        #pragma unroll
        for (int cp = 0; cp < 2; cp++) {
            const int chl = wid * 2 + cp;          // 0..15 channel within chunk
            const int cg = chl >> 2, cq = chl & 3;
            // patch frag (n16k16 -> two n8 frags)
            uint32_t brow = ((lane >> 4) << 3) + (lane & 7) + cg * 16;
            uint32_t bc16 = cq * 2 + ((lane >> 3) & 1);
            uint32_t bf[4];
            ldm4(bbase + brow * 128 + ((bc16 ^ (brow & 7)) << 4), bf);

            float zc[4][2][4];
            #pragma unroll
            for (int mi = 0; mi < 4; mi++)
                #pragma unroll
                for (int nj = 0; nj < 2; nj++)
                    #pragma unroll
                    for (int q = 0; q < 4; q++) zc[mi][nj][q] = 0.f;

            #pragma unroll
            for (int mi = 0; mi < 4; mi++) {
                uint32_t wrow = mi * 16 + (lane & 15) + cg * 64;
                uint32_t wc16 = cq * 2 + (lane >> 4);
                uint32_t a[4];
                ldm4(wbase + wrow * 128 + ((wc16 ^ (wrow & 7)) << 4), a);
                hmma(zc[mi][0], a, &bf[0]);
                hmma(zc[mi][1], a, &bf[2]);
            }
            // store Z[chl][m = o*16+p] as packed fp16 pairs (p, p+1)
            #pragma unroll
            for (int mi = 0; mi < 4; mi++)
                #pragma unroll
                for (int nj = 0; nj < 2; nj++)
                    #pragma unroll
                    for (int rq = 0; rq < 2; rq++) {
                        int o = mi * 16 + (lane >> 2) + rq * 8;
                        int p = nj * 8 + (lane & 3) * 2;
                        int m = o * 16 + p;
                        __half2 hv = __floats2half2_rn(zc[mi][nj][rq * 2],
                                                       zc[mi][nj][rq * 2 + 1]);
                        *(__half2*)(smem + SM_Z + s * 33024 + chl * ZPITCH + m * 2) = hv;
                    }
        }
        __syncthreads();

        // ---- stage 2: acc[m128][b16] += Z^T frag x s frag ----
        uint32_t sf0[2], sf1[2];
        {
            int c0 = (chk * 16 + (lane & 3) * 2) * 2;   // byte offset of channel pair
            const char* sp = smem + SM_S;
            sf0[0] = *(const uint32_t*)(sp + (lane >> 2) * 1040 + c0);
            sf0[1] = *(const uint32_t*)(sp + (lane >> 2) * 1040 + c0 + 16);
            sf1[0] = *(const uint32_t*)(sp + (8 + (lane >> 2)) * 1040 + c0);
            sf1[1] = *(const uint32_t*)(sp + (8 + (lane >> 2)) * 1040 + c0 + 16);
        }
        #pragma unroll
        for (int mi = 0; mi < 8; mi++) {
            int m0 = wid * 128 + mi * 16;
            uint32_t zaddr = zbase + ((lane & 7) + ((lane >> 4) & 1) * 8) * ZPITCH
                             + (m0 + ((lane >> 3) & 1) * 8) * 2;
            uint32_t z[4];
            ldm4t(zaddr, z);
            hmma(acc[mi][0], z, sf0);
            hmma(acc[mi][1], z, sf1);
        }
    }

    // ---------------- epilogue ----------------
    __syncthreads();
    // staging [m 1024][b 16] fp32, pitch 68B (conflict-free); scalar stores (4B aligned)
    #pragma unroll
    for (int mi = 0; mi < 8; mi++)
        #pragma unroll
        for (int nb = 0; nb < 2; nb++)
            #pragma unroll
            for (int rq = 0; rq < 2; rq++) {
                int m = wid * 128 + mi * 16 + (lane >> 2) + rq * 8;
                int b = nb * 8 + (lane & 3) * 2;
                *(float*)(smem + m * 68 + b * 4)     = acc[mi][nb][rq * 2];
                *(float*)(smem + m * 68 + b * 4 + 4) = acc[mi][nb][rq * 2 + 1];
            }
    __syncthreads();

    const int b = tid >> 4, p = tid & 15;
    const int pix = pbase + p;
    const float nzv = nzc[pix] * nzs[0];
    const float gain = 1.4142135623730951f;
    const float* dcp = g_dcoef + b * 512 + obase;
    const float* rw = g_rwp + b * 1536 + obase;
    float pr0 = 0.f, pr1 = 0.f, pr2 = 0.f;
    float* outb = out + ((size_t)b * 512 + obase) * HW + pix;
    #pragma unroll 4
    for (int o = 0; o < 64; o++) {
        float v = *(const float*)(smem + (o * 16 + p) * 68 + b * 4);
        float z = fmaf(v, dcp[o], nzv + cb[obase + o]);
        float x = (z > 0.f ? z : 0.2f * z) * gain;
        outb[(size_t)o * HW] = x;
        pr0 = fmaf(rw[o], x, pr0);
        pr1 = fmaf(rw[512 + o], x, pr1);
        pr2 = fmaf(rw[1024 + o], x, pr2);
    }
    float* ib = img + (size_t)b * 3 * HW + pix;
    atomicAdd(ib, pr0);
    atomicAdd(ib + HW, pr1);
    atomicAdd(ib + 2 * HW, pr2);
}

extern "C" void kernel_launch(void* const* d_in, const int* in_sizes, int n_in,
                              void* d_out, int out_size) {
    const float* ws   = (const float*)d_in[0];
    const float* cst  = (const float*)d_in[1];
    const float* cw   = (const float*)d_in[2];
    const float* cb   = (const float*)d_in[3];
    const float* caw  = (const float*)d_in[4];
    const float* cab  = (const float*)d_in[5];
    const float* nzc  = (const float*)d_in[6];
    const float* nzs  = (const float*)d_in[7];
    const float* rgbw = (const float*)d_in[8];
    const float* rgbb = (const float*)d_in[9];
    const float* raw  = (const float*)d_in[10];
    const float* rab  = (const float*)d_in[11];
    float* out = (float*)d_out;
    float* img = out + (size_t)BATCH * CH * HW;

    cudaFuncSetAttribute(k_fact, cudaFuncAttributeMaxDynamicSharedMemorySize, SM_TOTAL);

    k_prep0<<<2048 + 768, 256>>>(ws, caw, cab, raw, rab, cw, rgbb, img);  // launch 0
    k_dcoef<<<1024 + 96, 256>>>(rgbw);                                    // launch 1
    k_prep1<<<2048 + 16384, 256>>>(cw, cst);                              // launch 2
    dim3 g(HW / PT, CH / OT);                                             // (256, 8)
    k_fact<<<g, FTHR, SM_TOTAL>>>(nzc, nzs, cb, out, img);                // launch 3 (profiled)
}

// round 17
// speedup vs baseline: 1.4815x; 1.1220x over previous
#include <cuda_runtime.h>
#include <cuda_fp16.h>
#include <math.h>
#include <stdint.h>

#define BATCH 16
#define CH 512
#define HW 4096
#define OT 32            // o per CTA
#define PT 16            // pixels per CTA
#define CC 16            // channels per chunk
#define NCHUNK 32
#define FTHR 256
#define ZPITCH 1040      // 512 m * 2B + 16B pad

// smem map (dynamic):
#define SM_W 0                        // W operand, 2 x 16384
#define SM_B 32768                    // patch operand, 2 x 8192
#define SM_Z 49152                    // Z, 16 ch x ZPITCH (single buffer)
#define SM_S 65792                    // s fp16, 16 rows x 1040B
#define SM_TOTAL (65792 + 16640)      // 82432 -> 2 CTAs/SM

// ---------------- scratch ----------------
__device__ float g_s[BATCH * CH];
__device__ float g_s2[BATCH * CH];
__device__ float g_dcoef[BATCH * CH];
__device__ float g_wsq[CH * CH];
__device__ float g_rwp[BATCH * 3 * CH];       // rgb_w[ch,o] * s2[b,o]
__device__ __half g_Wp[128 * 512 * 64];       // [cgroup][o][4ch x 16k] (8.4MB)
__device__ __half g_Bp[128 * 4096 * 64];      // [cgroup][p][4ch x 16k] (67MB)

__device__ __forceinline__ uint32_t s2u(const void* p) {
    return (uint32_t)__cvta_generic_to_shared(p);
}
__device__ __forceinline__ void cpa16(uint32_t s, const void* g) {
    asm volatile("cp.async.cg.shared.global [%0], [%1], 16;" :: "r"(s), "l"(g));
}
__device__ __forceinline__ void ldm4(uint32_t addr, uint32_t* r) {
    asm volatile("ldmatrix.sync.aligned.m8n8.x4.shared.b16 {%0,%1,%2,%3}, [%4];"
                 : "=r"(r[0]), "=r"(r[1]), "=r"(r[2]), "=r"(r[3]) : "r"(addr));
}
__device__ __forceinline__ void ldm4t(uint32_t addr, uint32_t* r) {
    asm volatile("ldmatrix.sync.aligned.m8n8.x4.trans.shared.b16 {%0,%1,%2,%3}, [%4];"
                 : "=r"(r[0]), "=r"(r[1]), "=r"(r[2]), "=r"(r[3]) : "r"(addr));
}
__device__ __forceinline__ void stm4(uint32_t addr, uint32_t r0, uint32_t r1,
                                     uint32_t r2, uint32_t r3) {
    asm volatile("stmatrix.sync.aligned.m8n8.x4.shared.b16 [%0], {%1,%2,%3,%4};"
                 :: "r"(addr), "r"(r0), "r"(r1), "r"(r2), "r"(r3));
}
__device__ __forceinline__ void hmma(float* d, const uint32_t* a, const uint32_t* bf) {
    asm volatile(
        "mma.sync.aligned.m16n8k16.row.col.f32.f16.f16.f32 "
        "{%0,%1,%2,%3}, {%4,%5,%6,%7}, {%8,%9}, {%0,%1,%2,%3};"
        : "+f"(d[0]), "+f"(d[1]), "+f"(d[2]), "+f"(d[3])
        : "r"(a[0]), "r"(a[1]), "r"(a[2]), "r"(a[3]), "r"(bf[0]), "r"(bf[1]));
}
__device__ __forceinline__ uint32_t f2h2(float a, float b) {
    __half2 h = __floats2half2_rn(a, b);
    return *(uint32_t*)&h;
}

// ---------------- prep0: styles + wsq + img bias init ----------------
__global__ void k_prep0(const float* __restrict__ ws, const float* __restrict__ caw,
                        const float* __restrict__ cab, const float* __restrict__ raw,
                        const float* __restrict__ rab, const float* __restrict__ cw,
                        const float* __restrict__ rgbb, float* __restrict__ img) {
    if (blockIdx.x < 1024) {
        int widx = blockIdx.x * 8 + (threadIdx.x >> 5);
        int lane = threadIdx.x & 31;
        int b = widx >> 9, c = widx & 511;
        const float* w0 = ws + b * 1024;
        const float* w1 = w0 + 512;
        const float* ca = caw + c * 512;
        const float* ra = raw + c * 512;
        float a1 = 0.f, a2 = 0.f;
        for (int d = lane; d < 512; d += 32) {
            a1 = fmaf(w0[d], ca[d], a1);
            a2 = fmaf(w1[d], ra[d], a2);
        }
        #pragma unroll
        for (int o = 16; o; o >>= 1) {
            a1 += __shfl_xor_sync(0xffffffffu, a1, o);
            a2 += __shfl_xor_sync(0xffffffffu, a2, o);
        }
        if (lane == 0) {
            g_s[b * 512 + c] = a1 + cab[c];
            g_s2[b * 512 + c] = (a2 + rab[c]) * 0.04419417382415922f;
        }
    } else if (blockIdx.x < 2048) {
        int idx = (blockIdx.x - 1024) * 256 + threadIdx.x;
        const float* p = cw + (size_t)idx * 9;
        float s = 0.f;
        #pragma unroll
        for (int k = 0; k < 9; k++) s = fmaf(p[k], p[k], s);
        g_wsq[idx] = s;
    } else {
        int idx = (blockIdx.x - 2048) * 256 + threadIdx.x;
        int ch = (idx >> 12) % 3;
        img[idx] = rgbb[ch];
    }
}

// ---------------- dcoef + rwp ----------------
__global__ void k_dcoef(const float* __restrict__ rgbw) {
    if (blockIdx.x < 1024) {
        int widx = blockIdx.x * 8 + (threadIdx.x >> 5);
        int lane = threadIdx.x & 31;
        int b = widx >> 9, o = widx & 511;
        const float* wq = g_wsq + o * 512;
        const float* sp = g_s + b * 512;
        float a = 0.f;
        for (int c = lane; c < 512; c += 32) {
            float sv = sp[c];
            a = fmaf(wq[c] * sv, sv, a);
        }
        #pragma unroll
        for (int off = 16; off; off >>= 1) a += __shfl_xor_sync(0xffffffffu, a, off);
        if (!lane) g_dcoef[b * 512 + o] = rsqrtf(a + 1e-8f);
    } else {
        int idx = (blockIdx.x - 1024) * 256 + threadIdx.x;
        int b = idx / 1536;
        int r = idx - b * 1536;
        int ch = r >> 9, o = r & 511;
        g_rwp[idx] = rgbw[ch * 512 + o] * g_s2[b * 512 + o];
    }
}

// ---------------- prep1: pack W and patches into k16-padded 4ch rows ----------------
__global__ void k_prep1(const float* __restrict__ cw, const float* __restrict__ cst) {
    if (blockIdx.x < 2048) {
        int idx = blockIdx.x * 256 + threadIdx.x;
        int pos8 = (idx & 7) * 8;
        int rem = idx >> 3;          // cg*512 + o
        int o = rem & 511;
        int cg = rem >> 9;
        __half h[8];
        #pragma unroll
        for (int j = 0; j < 8; j++) {
            int pos = pos8 + j;
            int ch = cg * 4 + (pos >> 4);
            int k = pos & 15;
            float v = (k < 9) ? cw[(size_t)o * 4608 + ch * 9 + k] : 0.f;
            h[j] = __float2half_rn(v);
        }
        *(uint4*)(g_Wp + (size_t)idx * 8) = *(const uint4*)h;
    } else {
        int idx = (blockIdx.x - 2048) * 256 + threadIdx.x;
        int pos8 = (idx & 7) * 8;
        int rem = idx >> 3;          // cg*4096 + p
        int p = rem & 4095;
        int cg = rem >> 12;
        int py = p >> 6, px = p & 63;
        __half h[8];
        #pragma unroll
        for (int j = 0; j < 8; j++) {
            int pos = pos8 + j;
            int ch = cg * 4 + (pos >> 4);
            int k = pos & 15;
            float v = 0.f;
            if (k < 9) {
                int ky = (unsigned)k / 3u;
                int kx = k - ky * 3;
                int yy = py + ky - 1;
                int xx = px + kx - 1;
                if ((unsigned)yy < 64u && (unsigned)xx < 64u)
                    v = cst[ch * 4096 + yy * 64 + xx];
            }
            h[j] = __float2half_rn(v);
        }
        *(uint4*)(g_Bp + (size_t)idx * 8) = *(const uint4*)h;
    }
}

// ---------------- factorized two-stage kernel: OT=32, 2 CTAs/SM ----------------
__global__ __launch_bounds__(FTHR, 2)
void k_fact(const float* __restrict__ nzc, const float* __restrict__ nzs,
            const float* __restrict__ cb, float* __restrict__ out,
            float* __restrict__ img) {
    extern __shared__ char smem[];
    const uint32_t sb = s2u(smem);
    const int tid = threadIdx.x;
    const int wid = tid >> 5;
    const int lane = tid & 31;
    const int pbase = blockIdx.x * PT;
    const int obase = blockIdx.y * OT;

    // s fp16 into padded smem rows (consumed after >=1 sync)
    for (int i = tid; i < 16 * 256; i += FTHR) {
        int b = i >> 8, c2 = (i & 255) * 2;
        __half2 v = __floats2half2_rn(g_s[b * 512 + c2], g_s[b * 512 + c2 + 1]);
        *(__half2*)(smem + SM_S + b * 1040 + c2 * 2) = v;
    }

    float acc[4][2][4];
    #pragma unroll
    for (int mi = 0; mi < 4; mi++)
        #pragma unroll
        for (int nb = 0; nb < 2; nb++)
            #pragma unroll
            for (int q = 0; q < 4; q++) acc[mi][nb][q] = 0.f;

    // fill W(16KB: 128 rows) + patches(8KB: 64 rows) for chunk CHK into buffer S
    #define FILLWB(CHK, S) do {                                                   \
        int cg0 = (CHK) * 4;                                                      \
        _Pragma("unroll")                                                         \
        for (int j = 0; j < 4; j++) {                                             \
            int idx = tid + j * FTHR;                                             \
            uint32_t row = idx >> 3, c16 = idx & 7;                               \
            int oo = row & 31, cgi = row >> 5;                                    \
            const char* src = (const char*)g_Wp +                                 \
                (((size_t)(cg0 + cgi) * 512 + obase + oo) << 7) + c16 * 16;       \
            cpa16(sb + SM_W + (S) * 16384 + row * 128 +                           \
                  ((c16 ^ (row & 7)) << 4), src);                                 \
        }                                                                         \
        _Pragma("unroll")                                                         \
        for (int j = 0; j < 2; j++) {                                             \
            int idx = tid + j * FTHR;                                             \
            uint32_t row = idx >> 3, c16 = idx & 7;                               \
            int pp = row & 15, cgi = row >> 4;                                    \
            const char* src = (const char*)g_Bp +                                 \
                (((size_t)(cg0 + cgi) * 4096 + pbase + pp) << 7) + c16 * 16;      \
            cpa16(sb + SM_B + (S) * 8192 + row * 128 +                            \
                  ((c16 ^ (row & 7)) << 4), src);                                 \
        }                                                                         \
        asm volatile("cp.async.commit_group;" ::: "memory");                      \
    } while (0)

    FILLWB(0, 0);

    for (int chk = 0; chk < NCHUNK; chk++) {
        asm volatile("cp.async.wait_group 0;" ::: "memory");
        __syncthreads();
        if (chk + 1 < NCHUNK) FILLWB(chk + 1, (chk + 1) & 1);

        const int s = chk & 1;
        const uint32_t wbase = sb + SM_W + s * 16384;
        const uint32_t bbase = sb + SM_B + s * 8192;
        const uint32_t zbase = sb + SM_Z;

        // ---- stage 1: each warp computes 2 channels of Z[o32,p16] ----
        #pragma unroll
        for (int cp = 0; cp < 2; cp++) {
            const int chl = wid * 2 + cp;          // 0..15
            const int cg = chl >> 2, cq = chl & 3;
            uint32_t brow = ((lane >> 4) << 3) + (lane & 7) + cg * 16;
            uint32_t bc16 = cq * 2 + ((lane >> 3) & 1);
            uint32_t bf[4];
            ldm4(bbase + brow * 128 + ((bc16 ^ (brow & 7)) << 4), bf);

            float zc[2][2][4];
            #pragma unroll
            for (int mi = 0; mi < 2; mi++)
                #pragma unroll
                for (int nj = 0; nj < 2; nj++)
                    #pragma unroll
                    for (int q = 0; q < 4; q++) zc[mi][nj][q] = 0.f;

            #pragma unroll
            for (int mi = 0; mi < 2; mi++) {
                uint32_t wrow = cg * 32 + mi * 16 + (lane & 15);
                uint32_t wc16 = cq * 2 + (lane >> 4);
                uint32_t a[4];
                ldm4(wbase + wrow * 128 + ((wc16 ^ (wrow & 7)) << 4), a);
                hmma(zc[mi][0], a, &bf[0]);
                hmma(zc[mi][1], a, &bf[2]);
            }
            // store Z via stmatrix: per mi, 4 tiles (oB x pB), d-frag == stmatrix layout
            #pragma unroll
            for (int mi = 0; mi < 2; mi++) {
                int t = lane >> 3, r = lane & 7;
                uint32_t addr = zbase + chl * ZPITCH +
                    (uint32_t)(((mi * 16 + (t >> 1) * 8 + r) * 16 + (t & 1) * 8) * 2);
                stm4(addr,
                     f2h2(zc[mi][0][0], zc[mi][0][1]),
                     f2h2(zc[mi][1][0], zc[mi][1][1]),
                     f2h2(zc[mi][0][2], zc[mi][0][3]),
                     f2h2(zc[mi][1][2], zc[mi][1][3]));
            }
        }
        __syncthreads();

        // ---- stage 2: acc[m512][b16] += Z^T frag x s frag ----
        uint32_t sf0[2], sf1[2];
        {
            int c0 = (chk * 16 + (lane & 3) * 2) * 2;
            const char* sp = smem + SM_S;
            sf0[0] = *(const uint32_t*)(sp + (lane >> 2) * 1040 + c0);
            sf0[1] = *(const uint32_t*)(sp + (lane >> 2) * 1040 + c0 + 16);
            sf1[0] = *(const uint32_t*)(sp + (8 + (lane >> 2)) * 1040 + c0);
            sf1[1] = *(const uint32_t*)(sp + (8 + (lane >> 2)) * 1040 + c0 + 16);
        }
        #pragma unroll
        for (int mi = 0; mi < 4; mi++) {
            int m0 = wid * 64 + mi * 16;
            uint32_t zaddr = zbase + ((lane & 7) + ((lane >> 4) & 1) * 8) * ZPITCH
                             + (m0 + ((lane >> 3) & 1) * 8) * 2;
            uint32_t z[4];
            ldm4t(zaddr, z);
            hmma(acc[mi][0], z, sf0);
            hmma(acc[mi][1], z, sf1);
        }
    }

    // ---------------- epilogue ----------------
    __syncthreads();
    // staging [m 512][b 16] fp32, pitch 68B; scalar stores (4B aligned)
    #pragma unroll
    for (int mi = 0; mi < 4; mi++)
        #pragma unroll
        for (int nb = 0; nb < 2; nb++)
            #pragma unroll
            for (int rq = 0; rq < 2; rq++) {
                int m = wid * 64 + mi * 16 + (lane >> 2) + rq * 8;
                int b = nb * 8 + (lane & 3) * 2;
                *(float*)(smem + m * 68 + b * 4)     = acc[mi][nb][rq * 2];
                *(float*)(smem + m * 68 + b * 4 + 4) = acc[mi][nb][rq * 2 + 1];
            }
    __syncthreads();

    const int b = tid >> 4, p = tid & 15;
    const int pix = pbase + p;
    const float nzv = nzc[pix] * nzs[0];
    const float gain = 1.4142135623730951f;
    const float* dcp = g_dcoef + b * 512 + obase;
    const float* rw = g_rwp + b * 1536 + obase;
    float pr0 = 0.f, pr1 = 0.f, pr2 = 0.f;
    float* outb = out + ((size_t)b * 512 + obase) * HW + pix;
    #pragma unroll 4
    for (int o = 0; o < OT; o++) {
        float v = *(const float*)(smem + (o * 16 + p) * 68 + b * 4);
        float z = fmaf(v, dcp[o], nzv + cb[obase + o]);
        float x = (z > 0.f ? z : 0.2f * z) * gain;
        outb[(size_t)o * HW] = x;
        pr0 = fmaf(rw[o], x, pr0);
        pr1 = fmaf(rw[512 + o], x, pr1);
        pr2 = fmaf(rw[1024 + o], x, pr2);
    }
    float* ib = img + (size_t)b * 3 * HW + pix;
    atomicAdd(ib, pr0);
    atomicAdd(ib + HW, pr1);
    atomicAdd(ib + 2 * HW, pr2);
}

extern "C" void kernel_launch(void* const* d_in, const int* in_sizes, int n_in,
                              void* d_out, int out_size) {
    const float* ws   = (const float*)d_in[0];
    const float* cst  = (const float*)d_in[1];
    const float* cw   = (const float*)d_in[2];
    const float* cb   = (const float*)d_in[3];
    const float* caw  = (const float*)d_in[4];
    const float* cab  = (const float*)d_in[5];
    const float* nzc  = (const float*)d_in[6];
    const float* nzs  = (const float*)d_in[7];
    const float* rgbw = (const float*)d_in[8];
    const float* rgbb = (const float*)d_in[9];
    const float* raw  = (const float*)d_in[10];
    const float* rab  = (const float*)d_in[11];
    float* out = (float*)d_out;
    float* img = out + (size_t)BATCH * CH * HW;

    cudaFuncSetAttribute(k_fact, cudaFuncAttributeMaxDynamicSharedMemorySize, SM_TOTAL);

    k_prep0<<<2048 + 768, 256>>>(ws, caw, cab, raw, rab, cw, rgbb, img);  // launch 0
    k_dcoef<<<1024 + 96, 256>>>(rgbw);                                    // launch 1
    k_prep1<<<2048 + 16384, 256>>>(cw, cst);                              // launch 2
    dim3 g(HW / PT, CH / OT);                                             // (256, 16)
    k_fact<<<g, FTHR, SM_TOTAL>>>(nzc, nzs, cb, out, img);                // launch 3 (profiled)
}